// round 5
// baseline (speedup 1.0000x reference)
#include <cuda_runtime.h>
#include <cuda.h>
#include <cstdint>

#define BB     16
#define CC     3
#define HH     512
#define WW     512
#define NH     63
#define NW     63
#define NN     (NH * NW)          // 3969
#define FDIM   768
#define KNB    8

#define BN_TOTAL     (BB * NN)                      // 63,504 patches
#define PPC          16                             // patches per TMA CTA
#define PATCH_CTAS   (BN_TOTAL / PPC)               // 3,969 (exact)
#define TPB          128

#define POS_FLOATS   (BB * NN * 2)                  // 127,008
#define EDGE_FLOATS  (BB * 2 * NN * KNB)            // 1,016,064
#define EXTRA_FLOATS (POS_FLOATS + EDGE_FLOATS)     // 1,143,072
#define EXTRA_BLOCKS ((EXTRA_FLOATS + TPB - 1) / TPB)   // 8,931

#define NBUF         8
#define LA           4                              // loads in flight
#define PATCH_BYTES  3072                           // 768 floats

#define CX(a, b) { int _lo = min(a, b); b = max(a, b); a = _lo; }

__device__ __forceinline__ uint32_t smem_u32(const void* p) {
    uint32_t a;
    asm("{ .reg .u64 t; cvta.to.shared.u64 t, %1; cvt.u32.u64 %0, t; }"
        : "=r"(a) : "l"(p));
    return a;
}

// ---------------------------------------------------------------------------
// One fused kernel.
//  blocks [0, EXTRA_BLOCKS): positions + edge_index (register kNN via sorted
//    insertion network; key = d2*4096+idx reproduces top_k(-d2) ordering).
//  blocks [EXTRA_BLOCKS, ...): patch mover, thread 0 only. For each of PPC
//    patches: 3D TMA load (box 16x16x3 floats) lands the patch in SMEM in
//    exact output order; 1D bulk-store pushes 3KB to gmem. 8 buffers,
//    4 loads ahead, wait_group.read gates buffer reuse. SM touches no data.
// ---------------------------------------------------------------------------
__global__ void __launch_bounds__(TPB)
fused_kernel(const __grid_constant__ CUtensorMap tmap,
             float* __restrict__ out)
{
    __shared__ __align__(1024) unsigned char sbuf[NBUF][PATCH_BYTES];
    __shared__ uint64_t smbar[NBUF];

    int bid = blockIdx.x;

    if (bid < EXTRA_BLOCKS) {
        int e = bid * TPB + threadIdx.x;
        if (e >= EXTRA_FLOATS) return;

        const long long P0 = (long long)BN_TOTAL * FDIM;

        if (e < POS_FLOATS) {
            int n = (e >> 1) % NN;
            out[P0 + e] = (float)((e & 1) ? (n % NW) : (n / NW));
            return;
        }

        int e2 = e - POS_FLOATS;
        int r  = e2 % (2 * NN * KNB);
        float v;
        if (r < NN * KNB) {
            v = (float)(r >> 3);                    // src row: node id
        } else {
            int q = r - NN * KNB;
            int n = q >> 3;
            int m = q & 7;
            int i = n / NW;
            int j = n % NW;

            int t0 = 0x7fffffff, t1 = 0x7fffffff, t2 = 0x7fffffff, t3 = 0x7fffffff;
            int t4 = 0x7fffffff, t5 = 0x7fffffff, t6 = 0x7fffffff, t7 = 0x7fffffff;
            #pragma unroll
            for (int di = -2; di <= 2; di++) {
                #pragma unroll
                for (int dj = -2; dj <= 2; dj++) {
                    if (di == 0 && dj == 0) continue;
                    int ii = i + di;
                    int jj = j + dj;
                    bool ok = (ii >= 0) & (ii < NH) & (jj >= 0) & (jj < NW);
                    int key = ok ? ((di*di + dj*dj) * 4096 + (ii * NW + jj))
                                 : 0x7fffffff;
                    int t8 = key;
                    CX(t7, t8); CX(t6, t7); CX(t5, t6); CX(t4, t5);
                    CX(t3, t4); CX(t2, t3); CX(t1, t2); CX(t0, t1);
                }
            }
            int a0 = (m & 1) ? t1 : t0;
            int a1 = (m & 1) ? t3 : t2;
            int a2 = (m & 1) ? t5 : t4;
            int a3 = (m & 1) ? t7 : t6;
            int b0 = (m & 2) ? a1 : a0;
            int b1 = (m & 2) ? a3 : a2;
            int sel = (m & 4) ? b1 : b0;
            v = (float)(sel & 4095);
        }
        out[P0 + POS_FLOATS + e2] = v;
        return;
    }

    // ---- TMA patch mover (single thread per CTA) ----
    if (threadIdx.x != 0) return;

    int p0 = (bid - EXTRA_BLOCKS) * PPC;
    uint32_t sb = smem_u32(sbuf);
    uint32_t mb = smem_u32(smbar);

    #pragma unroll
    for (int s = 0; s < NBUF; s++)
        asm volatile("mbarrier.init.shared.b64 [%0], 1;"
                     :: "r"(mb + s * 8) : "memory");
    asm volatile("fence.proxy.async.shared::cta;" ::: "memory");

    auto issue_load = [&](int q) {
        int s  = q & (NBUF - 1);
        int bn = p0 + q;
        int b  = bn / NN;
        int n  = bn % NN;
        int cy = (n / NW) * 8;
        int cx = (n % NW) * 8;
        int cz = b * CC;
        uint32_t bar = mb + s * 8;
        asm volatile("mbarrier.arrive.expect_tx.shared.b64 _, [%0], %1;"
                     :: "r"(bar), "r"((uint32_t)PATCH_BYTES) : "memory");
        asm volatile(
            "cp.async.bulk.tensor.3d.shared::cta.global.tile.mbarrier::complete_tx::bytes "
            "[%0], [%1, {%2, %3, %4}], [%5];"
            :: "r"(sb + s * PATCH_BYTES), "l"(&tmap),
               "r"(cx), "r"(cy), "r"(cz), "r"(bar)
            : "memory");
    };

    #pragma unroll
    for (int q = 0; q < LA; q++) issue_load(q);

    for (int p = 0; p < PPC; p++) {
        int s  = p & (NBUF - 1);
        int ph = (p >> 3) & 1;
        uint32_t bar = mb + s * 8;

        // wait for load completion (spin on try_wait parity)
        uint32_t done = 0;
        while (!done) {
            asm volatile(
                "{ .reg .pred p;"
                "  mbarrier.try_wait.parity.acquire.cta.shared::cta.b64 p, [%1], %2, 0x989680;"
                "  selp.b32 %0, 1, 0, p; }"
                : "=r"(done) : "r"(bar), "r"((uint32_t)ph) : "memory");
        }

        // bulk store patch to gmem
        const char* gdst = (const char*)out + (long long)(p0 + p) * PATCH_BYTES;
        asm volatile("cp.async.bulk.global.shared::cta.bulk_group [%0], [%1], %2;"
                     :: "l"(gdst), "r"(sb + s * PATCH_BYTES),
                        "r"((uint32_t)PATCH_BYTES) : "memory");
        asm volatile("cp.async.bulk.commit_group;" ::: "memory");

        int nxt = p + LA;
        if (nxt < PPC) {
            // buffer for nxt was stored at iteration nxt-NBUF; ensure its
            // SMEM has been fully read (<= LA groups still pending)
            asm volatile("cp.async.bulk.wait_group.read 4;" ::: "memory");
            issue_load(nxt);
        }
    }
    asm volatile("cp.async.bulk.wait_group 0;" ::: "memory");
}

// ---------------------------------------------------------------------------
extern "C" void kernel_launch(void* const* d_in, const int* in_sizes, int n_in,
                              void* d_out, int out_size)
{
    const float* x = (const float*)d_in[0];
    float* out = (float*)d_out;

    // Build tensormap for x viewed as (W=512, H=512, B*C=48) fp32.
    typedef CUresult (*EncodeFn)(
        CUtensorMap*, CUtensorMapDataType, cuuint32_t, void*,
        const cuuint64_t*, const cuuint64_t*, const cuuint32_t*,
        const cuuint32_t*, CUtensorMapInterleave, CUtensorMapSwizzle,
        CUtensorMapL2promotion, CUtensorMapFloatOOBfill);
    EncodeFn encode = nullptr;
    cudaGetDriverEntryPoint("cuTensorMapEncodeTiled", (void**)&encode,
                            cudaEnableDefault, nullptr);

    CUtensorMap tmap;
    cuuint64_t dims[3]    = {WW, HH, (cuuint64_t)(BB * CC)};
    cuuint64_t strides[2] = {WW * sizeof(float),
                             (cuuint64_t)HH * WW * sizeof(float)};
    cuuint32_t box[3]     = {16, 16, CC};
    cuuint32_t estr[3]    = {1, 1, 1};
    encode(&tmap, CU_TENSOR_MAP_DATA_TYPE_FLOAT32, 3, (void*)x,
           dims, strides, box, estr,
           CU_TENSOR_MAP_INTERLEAVE_NONE, CU_TENSOR_MAP_SWIZZLE_NONE,
           CU_TENSOR_MAP_L2_PROMOTION_L2_128B,
           CU_TENSOR_MAP_FLOAT_OOB_FILL_NONE);

    fused_kernel<<<EXTRA_BLOCKS + PATCH_CTAS, TPB>>>(tmap, out);
}

// round 6
// speedup vs baseline: 1.0735x; 1.0735x over previous
#include <cuda_runtime.h>
#include <cuda.h>
#include <cstdint>

#define BB     16
#define CC     3
#define HH     512
#define WW     512
#define NH     63
#define NW     63
#define NN     (NH * NW)          // 3969
#define FDIM   768
#define KNB    8
#define F4PER  192

#define TPB    256

// patch tiling: 4 patch-rows x 8 patch-cols per CTA
#define TI     4
#define TJ     8
#define ITILES ((NH + TI - 1) / TI)     // 16
#define JTILES ((NW + TJ - 1) / TJ)     // 8
#define PATCH_CTAS (BB * ITILES * JTILES)   // 2048

// input stripe per CTA: 3 ch x 40 rows x 72 cols (floats)
#define SROWS  (TI * 8 + 8)             // 40
#define SCOLS  (TJ * 8 + 8)             // 72
#define STRIPE_FLOATS (CC * SROWS * SCOLS)  // 25,920
#define STRIPE_BYTES  (STRIPE_FLOATS * 4)   // 103,680? no: 25,920*4 = 103,680  -- wait
// 3*40*72 = 8640 floats = 34,560 bytes
#undef  STRIPE_FLOATS
#define STRIPE_FLOATS (CC * SROWS * SCOLS)  // 8640
#define STRIPE_BYTES  (STRIPE_FLOATS * 4)   // 34,560

#define POS_FLOATS   (BB * NN * 2)                  // 127,008
#define EDGE_FLOATS  (BB * 2 * NN * KNB)            // 1,016,064
#define EXTRA_FLOATS (POS_FLOATS + EDGE_FLOATS)     // 1,143,072
#define EXTRA_BLOCKS ((EXTRA_FLOATS + TPB - 1) / TPB)   // 4,466

#define CX(a, b) { int _lo = min(a, b); b = max(a, b); a = _lo; }

__device__ __forceinline__ uint32_t smem_u32(const void* p) {
    uint32_t a;
    asm("{ .reg .u64 t; cvta.to.shared.u64 t, %1; cvt.u32.u64 %0, t; }"
        : "=r"(a) : "l"(p));
    return a;
}

// ---------------------------------------------------------------------------
// One fused kernel.
//  blocks [0, EXTRA_BLOCKS): positions + edge_index (register kNN, sorted
//    insertion network; key = d2*4096+idx reproduces top_k(-d2) ordering).
//  blocks [EXTRA_BLOCKS, ...): patch tile. One TMA load stages the 40x72x3
//    input stripe in SMEM (reuse lives in SMEM, not L2); 256 threads emit
//    32 patches as LDS.128 -> STG.128 streaming stores.
// ---------------------------------------------------------------------------
__global__ void __launch_bounds__(TPB)
fused_kernel(const __grid_constant__ CUtensorMap tmap,
             float* __restrict__ out)
{
    __shared__ __align__(128) float s_in[STRIPE_FLOATS];  // [c][row][col], col=72
    __shared__ uint64_t s_bar;

    int bid = blockIdx.x;

    if (bid < EXTRA_BLOCKS) {
        int e = bid * TPB + threadIdx.x;
        if (e >= EXTRA_FLOATS) return;

        const long long P0 = (long long)BB * NN * FDIM;

        if (e < POS_FLOATS) {
            int n = (e >> 1) % NN;
            out[P0 + e] = (float)((e & 1) ? (n % NW) : (n / NW));
            return;
        }

        int e2 = e - POS_FLOATS;
        int r  = e2 % (2 * NN * KNB);
        float v;
        if (r < NN * KNB) {
            v = (float)(r >> 3);                    // src row: node id
        } else {
            int q = r - NN * KNB;
            int n = q >> 3;
            int m = q & 7;
            int i = n / NW;
            int j = n % NW;

            int t0 = 0x7fffffff, t1 = 0x7fffffff, t2 = 0x7fffffff, t3 = 0x7fffffff;
            int t4 = 0x7fffffff, t5 = 0x7fffffff, t6 = 0x7fffffff, t7 = 0x7fffffff;
            #pragma unroll
            for (int di = -2; di <= 2; di++) {
                #pragma unroll
                for (int dj = -2; dj <= 2; dj++) {
                    if (di == 0 && dj == 0) continue;
                    int ii = i + di;
                    int jj = j + dj;
                    bool ok = (ii >= 0) & (ii < NH) & (jj >= 0) & (jj < NW);
                    int key = ok ? ((di*di + dj*dj) * 4096 + (ii * NW + jj))
                                 : 0x7fffffff;
                    int t8 = key;
                    CX(t7, t8); CX(t6, t7); CX(t5, t6); CX(t4, t5);
                    CX(t3, t4); CX(t2, t3); CX(t1, t2); CX(t0, t1);
                }
            }
            int a0 = (m & 1) ? t1 : t0;
            int a1 = (m & 1) ? t3 : t2;
            int a2 = (m & 1) ? t5 : t4;
            int a3 = (m & 1) ? t7 : t6;
            int b0 = (m & 2) ? a1 : a0;
            int b1 = (m & 2) ? a3 : a2;
            int sel = (m & 4) ? b1 : b0;
            v = (float)(sel & 4095);
        }
        out[P0 + POS_FLOATS + e2] = v;
        return;
    }

    // ---- patch tile ----
    int t  = bid - EXTRA_BLOCKS;          // < 2048
    int jt = t & (JTILES - 1);            // 0..7
    int it = (t >> 3) & (ITILES - 1);     // 0..15
    int b  = t >> 7;                      // 0..15

    int i0 = it * TI;
    int j0 = jt * TJ;

    // TMA-stage the input stripe (OOB rows/cols zero-filled, never emitted)
    uint32_t sb  = smem_u32(s_in);
    uint32_t bar = smem_u32(&s_bar);

    if (threadIdx.x == 0)
        asm volatile("mbarrier.init.shared.b64 [%0], 1;" :: "r"(bar) : "memory");
    asm volatile("fence.proxy.async.shared::cta;" ::: "memory");
    __syncthreads();

    if (threadIdx.x == 0) {
        asm volatile("mbarrier.arrive.expect_tx.shared.b64 _, [%0], %1;"
                     :: "r"(bar), "r"((uint32_t)STRIPE_BYTES) : "memory");
        asm volatile(
            "cp.async.bulk.tensor.3d.shared::cta.global.tile.mbarrier::complete_tx::bytes "
            "[%0], [%1, {%2, %3, %4}], [%5];"
            :: "r"(sb), "l"(&tmap),
               "r"(j0 * 8), "r"(i0 * 8), "r"(b * CC), "r"(bar)
            : "memory");
    }
    // all threads wait for the load
    {
        uint32_t done = 0;
        while (!done) {
            asm volatile(
                "{ .reg .pred p;"
                "  mbarrier.try_wait.parity.acquire.cta.shared::cta.b64 p, [%1], %2, 0x989680;"
                "  selp.b32 %0, 1, 0, p; }"
                : "=r"(done) : "r"(bar), "r"(0u) : "memory");
        }
    }

    // emit 32 patches: warp w -> patches 4w..4w+3; lane covers float4 r
    int w    = threadIdx.x >> 5;
    int lane = threadIdx.x & 31;

    #pragma unroll
    for (int q = 0; q < 4; q++) {
        int p  = w * 4 + q;
        int pi = p >> 3;
        int pj = p & 7;
        int i  = i0 + pi;
        int j  = j0 + pj;
        if (i >= NH || j >= NW) continue;

        long long obase = (long long)(b * NN + i * NW + j) * F4PER;
        float4* dst = reinterpret_cast<float4*>(out) + obase;

        #pragma unroll
        for (int itr = 0; itr < 6; itr++) {
            int r  = itr * 32 + lane;          // 0..191
            int c  = r >> 6;
            int u  = (r >> 2) & 15;
            int vg = r & 3;
            const float4 v = *reinterpret_cast<const float4*>(
                &s_in[(c * SROWS + pi * 8 + u) * SCOLS + pj * 8 + vg * 4]);
            __stcs(dst + r, v);
        }
    }
}

// ---------------------------------------------------------------------------
extern "C" void kernel_launch(void* const* d_in, const int* in_sizes, int n_in,
                              void* d_out, int out_size)
{
    const float* x = (const float*)d_in[0];
    float* out = (float*)d_out;

    typedef CUresult (*EncodeFn)(
        CUtensorMap*, CUtensorMapDataType, cuuint32_t, void*,
        const cuuint64_t*, const cuuint64_t*, const cuuint32_t*,
        const cuuint32_t*, CUtensorMapInterleave, CUtensorMapSwizzle,
        CUtensorMapL2promotion, CUtensorMapFloatOOBfill);
    EncodeFn encode = nullptr;
    cudaGetDriverEntryPoint("cuTensorMapEncodeTiled", (void**)&encode,
                            cudaEnableDefault, nullptr);

    CUtensorMap tmap;
    cuuint64_t dims[3]    = {WW, HH, (cuuint64_t)(BB * CC)};
    cuuint64_t strides[2] = {WW * sizeof(float),
                             (cuuint64_t)HH * WW * sizeof(float)};
    cuuint32_t box[3]     = {SCOLS, SROWS, CC};   // 72 x 40 x 3 floats
    cuuint32_t estr[3]    = {1, 1, 1};
    encode(&tmap, CU_TENSOR_MAP_DATA_TYPE_FLOAT32, 3, (void*)x,
           dims, strides, box, estr,
           CU_TENSOR_MAP_INTERLEAVE_NONE, CU_TENSOR_MAP_SWIZZLE_NONE,
           CU_TENSOR_MAP_L2_PROMOTION_L2_128B,
           CU_TENSOR_MAP_FLOAT_OOB_FILL_NONE);

    fused_kernel<<<EXTRA_BLOCKS + PATCH_CTAS, TPB>>>(tmap, out);
}

// round 7
// speedup vs baseline: 1.1807x; 1.0999x over previous
#include <cuda_runtime.h>
#include <cuda.h>
#include <cstdint>

#define BB     16
#define CC     3
#define HH     512
#define WW     512
#define NH     63
#define NW     63
#define NN     (NH * NW)          // 3969
#define FDIM   768
#define KNB    8
#define F4PER  192

#define TPB    256

// tile = 4x4 patches; stripe = 3ch x 40 x 40 floats = 19200 B
#define TI     4
#define TJ     4
#define ITILES 16
#define JTILES 16
#define TILES  (BB * ITILES * JTILES)   // 4096
#define TILES_PER_CTA 4
#define PATCH_CTAS (TILES / TILES_PER_CTA)  // 1024

#define SROWS  40
#define SCOLS  40
#define STRIPE_FLOATS (CC * SROWS * SCOLS)  // 4800
#define STRIPE_BYTES  (STRIPE_FLOATS * 4)   // 19200

#define POS_FLOATS   (BB * NN * 2)                  // 127,008
#define EDGE_FLOATS  (BB * 2 * NN * KNB)            // 1,016,064
#define EXTRA_FLOATS (POS_FLOATS + EDGE_FLOATS)     // 1,143,072
#define EXTRA_BLOCKS ((EXTRA_FLOATS + TPB - 1) / TPB)   // 4,466

#define CX(a, b) { int _lo = min(a, b); b = max(a, b); a = _lo; }

__device__ __forceinline__ uint32_t smem_u32(const void* p) {
    uint32_t a;
    asm("{ .reg .u64 t; cvta.to.shared.u64 t, %1; cvt.u32.u64 %0, t; }"
        : "=r"(a) : "l"(p));
    return a;
}

// ---------------------------------------------------------------------------
// One fused kernel.
//  blocks [0, PATCH_CTAS): persistent patch movers. 4 tiles per CTA,
//    double-buffered TMA prefetch: emit tile q from buf q&1 while the load
//    for q+1 is in flight; issue q+2 right after the emit's syncthreads.
//  blocks [PATCH_CTAS, ...): positions + edge_index (register kNN, sorted
//    insertion network; key = d2*4096+idx reproduces top_k(-d2) ordering).
// ---------------------------------------------------------------------------
__global__ void __launch_bounds__(TPB)
fused_kernel(const __grid_constant__ CUtensorMap tmap,
             float* __restrict__ out)
{
    __shared__ __align__(128) float s_in[2][STRIPE_FLOATS];
    __shared__ uint64_t s_bar[2];

    int bid = blockIdx.x;

    if (bid >= PATCH_CTAS) {
        int e = (bid - PATCH_CTAS) * TPB + threadIdx.x;
        if (e >= EXTRA_FLOATS) return;

        const long long P0 = (long long)BB * NN * FDIM;

        if (e < POS_FLOATS) {
            int n = (e >> 1) % NN;
            out[P0 + e] = (float)((e & 1) ? (n % NW) : (n / NW));
            return;
        }

        int e2 = e - POS_FLOATS;
        int r  = e2 % (2 * NN * KNB);
        float v;
        if (r < NN * KNB) {
            v = (float)(r >> 3);                    // src row: node id
        } else {
            int q = r - NN * KNB;
            int n = q >> 3;
            int m = q & 7;
            int i = n / NW;
            int j = n % NW;

            int t0 = 0x7fffffff, t1 = 0x7fffffff, t2 = 0x7fffffff, t3 = 0x7fffffff;
            int t4 = 0x7fffffff, t5 = 0x7fffffff, t6 = 0x7fffffff, t7 = 0x7fffffff;
            #pragma unroll
            for (int di = -2; di <= 2; di++) {
                #pragma unroll
                for (int dj = -2; dj <= 2; dj++) {
                    if (di == 0 && dj == 0) continue;
                    int ii = i + di;
                    int jj = j + dj;
                    bool ok = (ii >= 0) & (ii < NH) & (jj >= 0) & (jj < NW);
                    int key = ok ? ((di*di + dj*dj) * 4096 + (ii * NW + jj))
                                 : 0x7fffffff;
                    int t8 = key;
                    CX(t7, t8); CX(t6, t7); CX(t5, t6); CX(t4, t5);
                    CX(t3, t4); CX(t2, t3); CX(t1, t2); CX(t0, t1);
                }
            }
            int a0 = (m & 1) ? t1 : t0;
            int a1 = (m & 1) ? t3 : t2;
            int a2 = (m & 1) ? t5 : t4;
            int a3 = (m & 1) ? t7 : t6;
            int b0 = (m & 2) ? a1 : a0;
            int b1 = (m & 2) ? a3 : a2;
            int sel = (m & 4) ? b1 : b0;
            v = (float)(sel & 4095);
        }
        out[P0 + POS_FLOATS + e2] = v;
        return;
    }

    // ---- persistent patch mover ----
    uint32_t sb0 = smem_u32(s_in[0]);
    uint32_t sb1 = smem_u32(s_in[1]);
    uint32_t mb  = smem_u32(s_bar);

    if (threadIdx.x == 0) {
        asm volatile("mbarrier.init.shared.b64 [%0], 1;" :: "r"(mb)     : "memory");
        asm volatile("mbarrier.init.shared.b64 [%0], 1;" :: "r"(mb + 8) : "memory");
        asm volatile("fence.proxy.async.shared::cta;" ::: "memory");
    }
    __syncthreads();

    int tile0 = bid * TILES_PER_CTA;

    auto issue_load = [&](int q) {   // thread 0 only
        int tile = tile0 + q;
        int b  = tile >> 8;
        int rr = tile & 255;
        int it = rr >> 4;
        int jt = rr & 15;
        uint32_t bar = mb + (q & 1) * 8;
        uint32_t dst = (q & 1) ? sb1 : sb0;
        asm volatile("mbarrier.arrive.expect_tx.shared.b64 _, [%0], %1;"
                     :: "r"(bar), "r"((uint32_t)STRIPE_BYTES) : "memory");
        asm volatile(
            "cp.async.bulk.tensor.3d.shared::cta.global.tile.mbarrier::complete_tx::bytes "
            "[%0], [%1, {%2, %3, %4}], [%5];"
            :: "r"(dst), "l"(&tmap),
               "r"(jt * 32), "r"(it * 32), "r"(b * CC), "r"(bar)
            : "memory");
    };

    if (threadIdx.x == 0) { issue_load(0); issue_load(1); }

    int w    = threadIdx.x >> 5;
    int lane = threadIdx.x & 31;

    for (int q = 0; q < TILES_PER_CTA; q++) {
        int tile = tile0 + q;
        int b  = tile >> 8;
        int rr = tile & 255;
        int it = rr >> 4;
        int jt = rr & 15;

        uint32_t bar = mb + (q & 1) * 8;
        uint32_t ph  = (q >> 1) & 1;
        const float* sin = s_in[q & 1];

        uint32_t done = 0;
        while (!done) {
            asm volatile(
                "{ .reg .pred p;"
                "  mbarrier.try_wait.parity.acquire.cta.shared::cta.b64 p, [%1], %2, 0x989680;"
                "  selp.b32 %0, 1, 0, p; }"
                : "=r"(done) : "r"(bar), "r"(ph) : "memory");
        }

        // emit 16 patches: warp w -> patches 2w, 2w+1
        #pragma unroll
        for (int pp = 0; pp < 2; pp++) {
            int p  = w * 2 + pp;
            int pi = p >> 2;
            int pj = p & 3;
            int i  = it * TI + pi;
            int j  = jt * TJ + pj;
            if (i < NH && j < NW) {
                float4* dst = reinterpret_cast<float4*>(out) +
                              (long long)(b * NN + i * NW + j) * F4PER;
                #pragma unroll
                for (int itr = 0; itr < 6; itr++) {
                    int r4 = itr * 32 + lane;          // 0..191
                    int c  = r4 >> 6;
                    int u  = (r4 >> 2) & 15;
                    int vg = r4 & 3;
                    const float4 v = *reinterpret_cast<const float4*>(
                        &sin[(c * SROWS + pi * 8 + u) * SCOLS + pj * 8 + vg * 4]);
                    __stcs(dst + r4, v);
                }
            }
        }

        __syncthreads();   // all reads of buf (q&1) done before reuse
        if (threadIdx.x == 0 && q + 2 < TILES_PER_CTA) issue_load(q + 2);
    }
}

// ---------------------------------------------------------------------------
extern "C" void kernel_launch(void* const* d_in, const int* in_sizes, int n_in,
                              void* d_out, int out_size)
{
    const float* x = (const float*)d_in[0];
    float* out = (float*)d_out;

    typedef CUresult (*EncodeFn)(
        CUtensorMap*, CUtensorMapDataType, cuuint32_t, void*,
        const cuuint64_t*, const cuuint64_t*, const cuuint32_t*,
        const cuuint32_t*, CUtensorMapInterleave, CUtensorMapSwizzle,
        CUtensorMapL2promotion, CUtensorMapFloatOOBfill);
    EncodeFn encode = nullptr;
    cudaGetDriverEntryPoint("cuTensorMapEncodeTiled", (void**)&encode,
                            cudaEnableDefault, nullptr);

    CUtensorMap tmap;
    cuuint64_t dims[3]    = {WW, HH, (cuuint64_t)(BB * CC)};
    cuuint64_t strides[2] = {WW * sizeof(float),
                             (cuuint64_t)HH * WW * sizeof(float)};
    cuuint32_t box[3]     = {SCOLS, SROWS, CC};   // 40 x 40 x 3 floats
    cuuint32_t estr[3]    = {1, 1, 1};
    encode(&tmap, CU_TENSOR_MAP_DATA_TYPE_FLOAT32, 3, (void*)x,
           dims, strides, box, estr,
           CU_TENSOR_MAP_INTERLEAVE_NONE, CU_TENSOR_MAP_SWIZZLE_NONE,
           CU_TENSOR_MAP_L2_PROMOTION_L2_128B,
           CU_TENSOR_MAP_FLOAT_OOB_FILL_NONE);

    fused_kernel<<<PATCH_CTAS + EXTRA_BLOCKS, TPB>>>(tmap, out);
}